// round 2
// baseline (speedup 1.0000x reference)
#include <cuda_runtime.h>
#include <math.h>

// Problem constants (shapes are fixed by the reference: [8,9,128,32,32])
#define BATCH 8
#define TT    9
#define CH    128
#define NPTS  1024          // 32*32 spatial points
#define PAIRS 64            // 8 * (9-1)
#define NFRAMES 72          // 8*9
#define NPASS 32            // init + 30 scan + final extrapolation
#define ROWBLKS 16          // 1024 rows / 64 rows per CTA

// ---------------- device scratch (static: no runtime allocation) ----------------
__device__ float  d_C[67108864];          // 64 * 1024 * 1024 cost matrix (256 MB, .nv.global NOBITS)
__device__ float  d_sq[NFRAMES * NPTS];   // per-point squared norms
__device__ float  d_chmin[CH], d_chmax[CH];
__device__ float  d_eps_pass[NPASS];      // eps for each pass
__device__ float  d_f[2][PAIRS * NPTS];   // ping-pong dual potentials
__device__ float  d_g[2][PAIRS * NPTS];
__device__ float  d_pmax[PAIRS * ROWBLKS * NPTS];  // per-rowblock column partial max (log2 units)
__device__ float  d_psum[PAIRS * ROWBLKS * NPTS];  // per-rowblock column partial sum
__device__ double d_loss;

__device__ __forceinline__ float ex2f_(float x) {
    float r; asm("ex2.approx.ftz.f32 %0, %1;" : "=f"(r) : "f"(x)); return r;
}
__device__ __forceinline__ float lg2f_(float x) {
    float r; asm("lg2.approx.f32 %0, %1;" : "=f"(r) : "f"(x)); return r;
}

// ---------------- per-channel min/max over the whole sequence ----------------
__global__ void smm_minmax_kernel(const float* __restrict__ seq) {
    int c = blockIdx.x, tid = threadIdx.x;
    float mn = 3.4e38f, mx = -3.4e38f;
    for (int i = tid; i < NFRAMES * NPTS; i += 256) {
        int bt = i >> 10, n = i & 1023;
        float v = seq[((size_t)bt * CH + c) * NPTS + n];
        mn = fminf(mn, v); mx = fmaxf(mx, v);
    }
    __shared__ float smn[256], smx[256];
    smn[tid] = mn; smx[tid] = mx; __syncthreads();
    for (int s = 128; s > 0; s >>= 1) {
        if (tid < s) { smn[tid] = fminf(smn[tid], smn[tid + s]);
                       smx[tid] = fmaxf(smx[tid], smx[tid + s]); }
        __syncthreads();
    }
    if (tid == 0) { d_chmin[c] = smn[0]; d_chmax[c] = smx[0]; }
}

// ---------------- diameter -> eps annealing schedule ----------------
__global__ void smm_init_kernel() {
    int tid = threadIdx.x;
    __shared__ float red[CH];
    float dd = d_chmax[tid] - d_chmin[tid];
    red[tid] = dd * dd; __syncthreads();
    for (int s = 64; s > 0; s >>= 1) {
        if (tid < s) red[tid] += red[tid + s];
        __syncthreads();
    }
    if (tid == 0) {
        float diam = sqrtf(red[0]) + 1e-6f;
        double ld = log((double)diam);
        double lb = log(0.1);                  // log(BLUR)
        d_eps_pass[0] = (float)exp(2.0 * ld);  // init pass: eps_list[0] = diam^2
        for (int k = 0; k < 30; k++) {         // scan passes 1..30: eps_list[0..29]
            double frac = (double)k / 29.0;
            d_eps_pass[k + 1] = (float)exp(2.0 * (ld + frac * (lb - ld)));
        }
        d_eps_pass[31] = 0.01f;                // final extrapolation: blur^2
        d_loss = 0.0;
    }
}

// ---------------- per-point squared norms ----------------
__global__ void smm_sq_kernel(const float* __restrict__ seq) {
    int bt = blockIdx.x;
    for (int n = threadIdx.x; n < NPTS; n += 256) {
        const float* p = seq + (size_t)bt * CH * NPTS + n;
        float s = 0.f;
        #pragma unroll 16
        for (int c = 0; c < CH; c++) { float v = p[(size_t)c * NPTS]; s = fmaf(v, v, s); }
        d_sq[bt * NPTS + n] = s;
    }
}

// ---------------- cost matrix: C = max(0, 0.5(|x|^2+|y|^2) - x.y) ----------------
// fp32 SIMT GEMM, 128x128 CTA tile, 8x8 microtile (split 4+4 for coalesced stores)
__global__ void __launch_bounds__(256) smm_cost_kernel(const float* __restrict__ seq) {
    int p = blockIdx.z, b = p >> 3, tt = p & 7;
    const float* X = seq + (size_t)(b * TT + tt)     * CH * NPTS;
    const float* Y = seq + (size_t)(b * TT + tt + 1) * CH * NPTS;
    int i0 = blockIdx.y * 128, j0 = blockIdx.x * 128;
    __shared__ float Xs[16][128], Ys[16][128];
    float acc[8][8];
    #pragma unroll
    for (int u = 0; u < 8; u++)
        #pragma unroll
        for (int v = 0; v < 8; v++) acc[u][v] = 0.f;
    int tid = threadIdx.x, tx = tid & 15, ty = tid >> 4;
    for (int k0 = 0; k0 < CH; k0 += 16) {
        #pragma unroll
        for (int q = 0; q < 8; q++) {
            int idx = tid + q * 256, kk = idx >> 7, cc = idx & 127;
            Xs[kk][cc] = X[(size_t)(k0 + kk) * NPTS + i0 + cc];
            Ys[kk][cc] = Y[(size_t)(k0 + kk) * NPTS + j0 + cc];
        }
        __syncthreads();
        #pragma unroll
        for (int k = 0; k < 16; k++) {
            float4 a0 = *(const float4*)&Xs[k][ty * 4];
            float4 a1 = *(const float4*)&Xs[k][64 + ty * 4];
            float4 b0 = *(const float4*)&Ys[k][tx * 4];
            float4 b1 = *(const float4*)&Ys[k][64 + tx * 4];
            float av[8] = {a0.x,a0.y,a0.z,a0.w,a1.x,a1.y,a1.z,a1.w};
            float bv[8] = {b0.x,b0.y,b0.z,b0.w,b1.x,b1.y,b1.z,b1.w};
            #pragma unroll
            for (int u = 0; u < 8; u++)
                #pragma unroll
                for (int v = 0; v < 8; v++) acc[u][v] = fmaf(av[u], bv[v], acc[u][v]);
        }
        __syncthreads();
    }
    const float* sqx = d_sq + (b * TT + tt)     * NPTS + i0;
    const float* sqy = d_sq + (b * TT + tt + 1) * NPTS + j0;
    float sy[8];
    #pragma unroll
    for (int v = 0; v < 8; v++) sy[v] = sqy[tx * 4 + (v & 3) + ((v >> 2) << 6)];
    float* Co = d_C + (size_t)p * NPTS * NPTS;
    #pragma unroll
    for (int u = 0; u < 8; u++) {
        int i = ty * 4 + (u & 3) + ((u >> 2) << 6);
        float sx = sqx[i];
        float4 o0, o1;
        o0.x = fmaxf(0.5f*(sx+sy[0]) - acc[u][0], 0.f);
        o0.y = fmaxf(0.5f*(sx+sy[1]) - acc[u][1], 0.f);
        o0.z = fmaxf(0.5f*(sx+sy[2]) - acc[u][2], 0.f);
        o0.w = fmaxf(0.5f*(sx+sy[3]) - acc[u][3], 0.f);
        o1.x = fmaxf(0.5f*(sx+sy[4]) - acc[u][4], 0.f);
        o1.y = fmaxf(0.5f*(sx+sy[5]) - acc[u][5], 0.f);
        o1.z = fmaxf(0.5f*(sx+sy[6]) - acc[u][6], 0.f);
        o1.w = fmaxf(0.5f*(sx+sy[7]) - acc[u][7], 0.f);
        *(float4*)&Co[(size_t)(i0 + i) * NPTS + j0 + tx * 4]      = o0;
        *(float4*)&Co[(size_t)(i0 + i) * NPTS + j0 + 64 + tx * 4] = o1;
    }
}

// ---------------- fused Sinkhorn sweep: one pass over C computes ----------------
//   ft_i (row logsumexp, completed per 64-row CTA strip)  and
//   per-strip column partials (max,sum) for gt_j.
// Everything in log2 units; eps folded into the tile at load time.
// flags: bit0 = treat f_in/g_in as zero (init pass), bit1 = average update,
//        bit2 = final pass (accumulate loss instead of writing potentials).
__global__ void __launch_bounds__(256) smm_sink_kernel(int pass, int flags) {
    __shared__ float Cs[128 * 65];   // column-major tile (col*65 + row), conflict-free both ways
    __shared__ float gsh[1024];      // g/eps * log2(e)
    __shared__ float fsh[64];        // f/eps * log2(e) for this row strip
    __shared__ float fraw[64];
    __shared__ float red[256];
    const float* f_in = d_f[pass & 1];
    const float* g_in = d_g[pass & 1];
    float* f_out = d_f[(pass + 1) & 1];
    int p = blockIdx.y, rb = blockIdx.x, tid = threadIdx.x;
    int zf = flags & 1, avg = flags & 2, fin = flags & 4;
    float eps = d_eps_pass[pass];
    float ivl = 1.4426950408889634f / eps;   // log2(e)/eps
    float nivl = -ivl;
    int r0 = rb * 64;
    for (int j = tid; j < 1024; j += 256) gsh[j] = zf ? 0.f : g_in[p * 1024 + j] * ivl;
    if (tid < 64) {
        float fv = zf ? 0.f : f_in[p * 1024 + r0 + tid];
        fraw[tid] = fv; fsh[tid] = fv * ivl;
    }
    __syncthreads();
    int row = tid >> 2, part = tid & 3;      // row sweep: 64 rows x 4 lanes (shfl partners)
    int ccol = tid >> 1, chalf = tid & 1;    // col sweep: 128 cols x 2 lanes
    float rm = -1e30f, rs = 0.f;             // running row (max,sum), identical across partners
    const float* Cp = d_C + (size_t)p * 1048576 + (size_t)r0 * 1024;
    for (int t8 = 0; t8 < 8; t8++) {
        int c0 = t8 << 7;
        #pragma unroll
        for (int q = 0; q < 32; q++) {       // load 64x128 tile, scaled by -log2e/eps
            int idx = tid + (q << 8), r = idx >> 7, col = idx & 127;
            Cs[col * 65 + r] = Cp[(size_t)r * 1024 + (c0 + col)] * nivl;
        }
        __syncthreads();
        // ---- row direction: v = (g_j - C_ij) * log2e/eps ----
        float v[32]; float lm = -1e30f;
        #pragma unroll
        for (int k = 0; k < 32; k++) {
            int cc = (part << 5) + ((k + (part << 3)) & 31);   // phase-rotated: conflict-free
            float x = Cs[cc * 65 + row] + gsh[c0 + cc];
            v[k] = x; lm = fmaxf(lm, x);
        }
        lm = fmaxf(lm, __shfl_xor_sync(0xffffffffu, lm, 1));
        lm = fmaxf(lm, __shfl_xor_sync(0xffffffffu, lm, 2));
        float nm = fmaxf(rm, lm);
        float ls = 0.f;
        #pragma unroll
        for (int k = 0; k < 32; k++) ls += ex2f_(v[k] - nm);
        ls += __shfl_xor_sync(0xffffffffu, ls, 1);
        ls += __shfl_xor_sync(0xffffffffu, ls, 2);
        rs = rs * ex2f_(rm - nm) + ls; rm = nm;
        // ---- column direction: w = (f_i - C_ij) * log2e/eps (this strip only) ----
        float w2[32]; float cmx = -1e30f;
        #pragma unroll
        for (int k = 0; k < 32; k++) {
            int rr = (chalf << 5) + ((k + (chalf << 4)) & 31);
            float x = Cs[ccol * 65 + rr] + fsh[rr];
            w2[k] = x; cmx = fmaxf(cmx, x);
        }
        cmx = fmaxf(cmx, __shfl_xor_sync(0xffffffffu, cmx, 1));
        float cls = 0.f;
        #pragma unroll
        for (int k = 0; k < 32; k++) cls += ex2f_(w2[k] - cmx);
        cls += __shfl_xor_sync(0xffffffffu, cls, 1);
        if (chalf == 0) {
            int o = (p * ROWBLKS + rb) * 1024 + c0 + ccol;
            d_pmax[o] = cmx; d_psum[o] = cls;
        }
        __syncthreads();
    }
    // ft = -eps * (logw + ln2*(rm + log2(rs)))  with logw = -ln(1024) = -10*ln2
    float ft = -eps * 0.69314718055994531f * (rm + lg2f_(rs) - 10.f);
    if (!fin) {
        if (part == 0) f_out[p * 1024 + r0 + row] = avg ? 0.5f * (fraw[row] + ft) : ft;
    } else {
        red[tid] = (part == 0) ? ft : 0.f;
        __syncthreads();
        for (int s = 128; s > 0; s >>= 1) {
            if (tid < s) red[tid] += red[tid + s];
            __syncthreads();
        }
        if (tid == 0) atomicAdd(&d_loss, (double)red[0]);
    }
}

// ---------------- merge 16 row-strip column partials -> gt_j ----------------
__global__ void smm_combine_kernel(int pass, int flags) {
    int gid = blockIdx.x * 256 + threadIdx.x;
    int p = gid >> 10, col = gid & 1023;
    const float* g_in = d_g[pass & 1];
    float* g_out = d_g[(pass + 1) & 1];
    int avg = flags & 2, fin = flags & 4;
    float eps = d_eps_pass[pass];
    float M = -1e30f;
    float pm[ROWBLKS], ps[ROWBLKS];
    #pragma unroll
    for (int b2 = 0; b2 < ROWBLKS; b2++) {
        int o = (p * ROWBLKS + b2) * 1024 + col;
        pm[b2] = d_pmax[o]; ps[b2] = d_psum[o];
        M = fmaxf(M, pm[b2]);
    }
    float S = 0.f;
    #pragma unroll
    for (int b2 = 0; b2 < ROWBLKS; b2++) S += ps[b2] * ex2f_(pm[b2] - M);
    float gt = -eps * 0.69314718055994531f * (M + lg2f_(S) - 10.f);
    if (!fin) {
        g_out[gid] = avg ? 0.5f * (g_in[gid] + gt) : gt;
    } else {
        __shared__ float red[256];
        red[threadIdx.x] = gt; __syncthreads();
        for (int s = 128; s > 0; s >>= 1) {
            if (threadIdx.x < s) red[threadIdx.x] += red[threadIdx.x + s];
            __syncthreads();
        }
        if (threadIdx.x == 0) atomicAdd(&d_loss, (double)red[0]);
    }
}

__global__ void smm_finalize_kernel(float* out, int n) {
    float v = (float)(d_loss * (1.0 / 65536.0));   // /(P*N)
    for (int i = threadIdx.x; i < n; i += 32) out[i] = v;
}

// ---------------- launch: fully graph-capturable, no allocs, no sync ----------------
extern "C" void kernel_launch(void* const* d_in, const int* in_sizes, int n_in,
                              void* d_out, int out_size) {
    const float* seq = (const float*)d_in[0];
    smm_minmax_kernel<<<CH, 256>>>(seq);
    smm_init_kernel<<<1, CH>>>();
    smm_sq_kernel<<<NFRAMES, 256>>>(seq);
    smm_cost_kernel<<<dim3(8, 8, PAIRS), 256>>>(seq);
    for (int pass = 0; pass < NPASS; ++pass) {
        int flags = (pass == 0 ? 1 : 0)
                  | ((pass >= 1 && pass <= 30) ? 2 : 0)
                  | (pass == 31 ? 4 : 0);
        smm_sink_kernel<<<dim3(ROWBLKS, PAIRS), 256>>>(pass, flags);
        smm_combine_kernel<<<PAIRS * NPTS / 256, 256>>>(pass, flags);
    }
    smm_finalize_kernel<<<1, 32>>>((float*)d_out, out_size);
}